// round 4
// baseline (speedup 1.0000x reference)
#include <cuda_runtime.h>
#include <math.h>

#define TPB 576
#define SMEM_FLOATS 27328
#define SMEM_BYTES (SMEM_FLOATS * 4)   // 109312 bytes -> 2 CTAs/SM

__device__ __forceinline__ float gelu_exact(float x) {
    return 0.5f * x * (1.0f + erff(x * 0.70710678118654752440f));
}

// 2-output x 4-n register-tile GEMM over SMEM, accumulation order identical to R2.
template<int CIN>
__device__ __forceinline__ void gemm2x4(const float* __restrict__ W,
                                        const float* __restrict__ X,
                                        int o0, int n0,
                                        float4& a0, float4& a1)
{
    a0 = make_float4(0.f, 0.f, 0.f, 0.f);
    a1 = make_float4(0.f, 0.f, 0.f, 0.f);
    const float* w0 = W + o0 * CIN;
    const float* w1 = w0 + CIN;
    #pragma unroll 16
    for (int c = 0; c < CIN; c++) {
        float wa = w0[c], wb = w1[c];
        float4 v = *(const float4*)&X[c * 144 + n0];
        a0.x = fmaf(wa, v.x, a0.x); a0.y = fmaf(wa, v.y, a0.y);
        a0.z = fmaf(wa, v.z, a0.z); a0.w = fmaf(wa, v.w, a0.w);
        a1.x = fmaf(wb, v.x, a1.x); a1.y = fmaf(wb, v.y, a1.y);
        a1.z = fmaf(wb, v.z, a1.z); a1.w = fmaf(wb, v.w, a1.w);
    }
}

__global__ void __launch_bounds__(TPB, 2) gcn_kernel(
    const float* __restrict__ gin,  const float* __restrict__ gpos, const float* __restrict__ grel,
    const float* __restrict__ gW1,  const float* __restrict__ gb1,
    const float* __restrict__ gWc,  const float* __restrict__ gbc,
    const float* __restrict__ gW2,  const float* __restrict__ gb2,
    const float* __restrict__ gF1,  const float* __restrict__ gfb1,
    const float* __restrict__ gF2,  const float* __restrict__ gfb2,
    float* __restrict__ gout)
{
    extern __shared__ float sm[];
    float* sW = sm;                   // 4096: W1(fc1) -> Wc(conv) -> [W2 | F1 | F2]
    float* sB = sW + 4096;            // 192: [0,32) b1 [32,96) bc [96,128) b2 [128,160) fb1 [160,192) fb2
    float* sT = sB + 192;             // 4608: tmp = in+pos, later x after grapher  [c][n]
    float* sS = sT + 4608;            // 9216: stacked [2C][n] (row 2c=xf, 2c+1=m); later ffn hidden rows 0..31
    float* sU = sS + 9216;            // 9216: union { sXn(5184)+sSq(144)+sIdx | sH conv out [64][n] }
    float* sXn = sU;                  // [n][c] stride 36
    float* sSq = sU + 5184;           // 144
    int*   sIdx = (int*)(sU + 5376);  // 144*9 ints
    float* sH = sU;                   // conv output (after MRConv consumed sXn/sIdx)

    const int tid = threadIdx.x;
    const int b   = blockIdx.x;
    const int q   = tid / 36;         // 0..15
    const int r   = tid - q * 36;     // 0..35
    const int n0  = r << 2;

    // ---------------- stage 0: W1 + biases + input(+pos) ----------------
    for (int i = tid; i < 256; i += TPB) ((float4*)sW)[i] = ((const float4*)gW1)[i];
    if (tid < 32)       sB[tid] = gb1[tid];
    else if (tid < 96)  sB[tid] = gbc[tid - 32];
    else if (tid < 128) sB[tid] = gb2[tid - 96];
    else if (tid < 160) sB[tid] = gfb1[tid - 128];
    else if (tid < 192) sB[tid] = gfb2[tid - 160];
    {
        const float4* gi4 = (const float4*)(gin + (size_t)b * 4608);
        const float4* gp4 = (const float4*)gpos;
        for (int i = tid; i < 1152; i += TPB) {
            float4 a = gi4[i], p = gp4[i];
            a.x += p.x; a.y += p.y; a.z += p.z; a.w += p.w;
            ((float4*)sT)[i] = a;
        }
    }
    __syncthreads();

    // ---------------- fc1: xf = W1 @ tmp + b1 -> sS even rows ----------------
    {
        int o0 = q << 1;
        float4 a0, a1;
        gemm2x4<32>(sW, sT, o0, n0, a0, a1);
        float bb0 = sB[o0], bb1 = sB[o0 + 1];
        a0.x += bb0; a0.y += bb0; a0.z += bb0; a0.w += bb0;
        a1.x += bb1; a1.y += bb1; a1.z += bb1; a1.w += bb1;
        *(float4*)&sS[(2 * o0) * 144 + n0]     = a0;
        *(float4*)&sS[(2 * o0 + 2) * 144 + n0] = a1;
    }
    __syncthreads();

    // ---------------- normalize (tid<144) in parallel with Wc load (tid>=144) ----------------
    if (tid < 144) {
        float v[32]; float s = 0.f;
        #pragma unroll
        for (int c = 0; c < 32; c++) { float x = sS[(2 * c) * 144 + tid]; v[c] = x; s = fmaf(x, x, s); }
        float nrm = fmaxf(sqrtf(s), 1e-12f);
        float sq = 0.f;
        #pragma unroll
        for (int c = 0; c < 32; c++) { float xn = v[c] / nrm; sXn[tid * 36 + c] = xn; sq = fmaf(xn, xn, sq); }
        sSq[tid] = sq;
    } else {
        for (int i = tid - 144; i < 1024; i += TPB - 144)
            ((float4*)sW)[i] = ((const float4*)gWc)[i];
    }
    __syncthreads();

    // ---------------- pairwise dist + top-9 ----------------
    // thread = row*4 + part: a row's 4 partial lists sit in 4 adjacent lanes -> shuffle merge
    {
        const int row  = tid >> 2;
        const int part = tid & 3;
        const float* xr = &sXn[row * 36];
        const float4 v0 = ((const float4*)xr)[0];
        const float4 v1 = ((const float4*)xr)[1];
        const float4 v2 = ((const float4*)xr)[2];
        const float4 v3 = ((const float4*)xr)[3];
        const float sqn = sSq[row];
        float bd[9]; int bi[9];
        #pragma unroll
        for (int k = 0; k < 9; k++) { bd[k] = 3.0e38f; bi[k] = 0; }
        int m = part * 36;
        const float* relp = grel + (size_t)m * 144 + row;
        for (int mm = 0; mm < 36; mm++, m++, relp += 144) {
            const float4* xm = (const float4*)&sXn[m * 36];
            float4 a;
            float d0, d1, d2, d3;
            a = xm[0]; d0 = v0.x * a.x; d1 = v0.y * a.y; d2 = v0.z * a.z; d3 = v0.w * a.w;
            a = xm[1]; d0 = fmaf(v1.x, a.x, d0); d1 = fmaf(v1.y, a.y, d1);
                       d2 = fmaf(v1.z, a.z, d2); d3 = fmaf(v1.w, a.w, d3);
            a = xm[2]; d0 = fmaf(v2.x, a.x, d0); d1 = fmaf(v2.y, a.y, d1);
                       d2 = fmaf(v2.z, a.z, d2); d3 = fmaf(v2.w, a.w, d3);
            a = xm[3]; d0 = fmaf(v3.x, a.x, d0); d1 = fmaf(v3.y, a.y, d1);
                       d2 = fmaf(v3.z, a.z, d2); d3 = fmaf(v3.w, a.w, d3);
            #pragma unroll
            for (int c4 = 4; c4 < 8; c4++) {           // second half streamed (reg budget)
                float4 vv = ((const float4*)xr)[c4];
                a = xm[c4];
                d0 = fmaf(vv.x, a.x, d0); d1 = fmaf(vv.y, a.y, d1);
                d2 = fmaf(vv.z, a.z, d2); d3 = fmaf(vv.w, a.w, d3);
            }
            float dot = (d0 + d1) + (d2 + d3);
            float d = (sqn - 2.0f * dot) + sSq[m] + *relp;
            if (d < bd[8]) {                     // strict-less: ties keep lower index
                bd[8] = d; bi[8] = m;
                #pragma unroll
                for (int j = 8; j > 0; --j) {
                    if (bd[j] < bd[j-1]) {
                        float td = bd[j]; bd[j] = bd[j-1]; bd[j-1] = td;
                        int   ti = bi[j]; bi[j] = bi[j-1]; bi[j-1] = ti;
                    }
                }
            }
        }
        // shuffle-merge parts 1..3 into part 0 (ascending m ranges preserve tie rule)
        #pragma unroll
        for (int src = 1; src < 4; src++) {
            #pragma unroll
            for (int k = 0; k < 9; k++) {
                float d  = __shfl_sync(0xFFFFFFFFu, bd[k], src, 4);
                int   mi = __shfl_sync(0xFFFFFFFFu, bi[k], src, 4);
                if (part == 0 && d < bd[8]) {
                    bd[8] = d; bi[8] = mi;
                    #pragma unroll
                    for (int j = 8; j > 0; --j) {
                        if (bd[j] < bd[j-1]) {
                            float td = bd[j]; bd[j] = bd[j-1]; bd[j-1] = td;
                            int   ti = bi[j]; bi[j] = bi[j-1]; bi[j-1] = ti;
                        }
                    }
                }
            }
        }
        if (part == 0) {
            #pragma unroll
            for (int k = 0; k < 9; k++) sIdx[row * 9 + k] = bi[k];
        }
    }
    __syncthreads();

    // ---------------- MRConv: thread = (n, 8-channel group); idx loaded once ----------------
    {
        const int n2 = tid % 144;
        const int g  = tid / 144;          // 0..3 -> channels g*8..g*8+7
        int idx9[9];
        #pragma unroll
        for (int k = 0; k < 9; k++) idx9[k] = sIdx[n2 * 9 + k];
        #pragma unroll
        for (int cc = 0; cc < 8; cc++) {
            int c = g * 8 + cc;
            const float* xrow = &sS[(2 * c) * 144];
            float xi = xrow[n2];
            float mx = -3.0e38f;
            #pragma unroll
            for (int k = 0; k < 9; k++) mx = fmaxf(mx, xrow[idx9[k]] - xi);
            sS[(2 * c + 1) * 144 + n2] = mx;
        }
    }
    __syncthreads();

    // ---------------- conv: hc = gelu(Wc @ stacked + bc), 4o x 4n tile -> sH ----------------
    {
        const int o0 = q << 2;             // 0..60
        float4 a0 = make_float4(0.f,0.f,0.f,0.f), a1 = a0, a2 = a0, a3 = a0;
        const float* w0 = &sW[o0 * 64];
        const float* w1 = w0 + 64;
        const float* w2 = w0 + 128;
        const float* w3 = w0 + 192;
        #pragma unroll 16
        for (int c = 0; c < 64; c++) {
            float4 v = *(const float4*)&sS[c * 144 + n0];
            float wa = w0[c], wb = w1[c], wc = w2[c], wd = w3[c];
            a0.x = fmaf(wa, v.x, a0.x); a0.y = fmaf(wa, v.y, a0.y);
            a0.z = fmaf(wa, v.z, a0.z); a0.w = fmaf(wa, v.w, a0.w);
            a1.x = fmaf(wb, v.x, a1.x); a1.y = fmaf(wb, v.y, a1.y);
            a1.z = fmaf(wb, v.z, a1.z); a1.w = fmaf(wb, v.w, a1.w);
            a2.x = fmaf(wc, v.x, a2.x); a2.y = fmaf(wc, v.y, a2.y);
            a2.z = fmaf(wc, v.z, a2.z); a2.w = fmaf(wc, v.w, a2.w);
            a3.x = fmaf(wd, v.x, a3.x); a3.y = fmaf(wd, v.y, a3.y);
            a3.z = fmaf(wd, v.z, a3.z); a3.w = fmaf(wd, v.w, a3.w);
        }
        float b0 = sB[32 + o0], b1 = sB[33 + o0], b2 = sB[34 + o0], b3 = sB[35 + o0];
        a0.x = gelu_exact(a0.x + b0); a0.y = gelu_exact(a0.y + b0);
        a0.z = gelu_exact(a0.z + b0); a0.w = gelu_exact(a0.w + b0);
        a1.x = gelu_exact(a1.x + b1); a1.y = gelu_exact(a1.y + b1);
        a1.z = gelu_exact(a1.z + b1); a1.w = gelu_exact(a1.w + b1);
        a2.x = gelu_exact(a2.x + b2); a2.y = gelu_exact(a2.y + b2);
        a2.z = gelu_exact(a2.z + b2); a2.w = gelu_exact(a2.w + b2);
        a3.x = gelu_exact(a3.x + b3); a3.y = gelu_exact(a3.y + b3);
        a3.z = gelu_exact(a3.z + b3); a3.w = gelu_exact(a3.w + b3);
        *(float4*)&sH[(o0 + 0) * 144 + n0] = a0;
        *(float4*)&sH[(o0 + 1) * 144 + n0] = a1;
        *(float4*)&sH[(o0 + 2) * 144 + n0] = a2;
        *(float4*)&sH[(o0 + 3) * 144 + n0] = a3;
    }
    __syncthreads();

    // ---------------- reload weights: [W2 | F1 | F2] ----------------
    for (int i = tid; i < 1024; i += TPB) {
        float4 v;
        if (i < 512)      v = ((const float4*)gW2)[i];
        else if (i < 768) v = ((const float4*)gF1)[i - 512];
        else              v = ((const float4*)gF2)[i - 768];
        ((float4*)sW)[i] = v;
    }
    __syncthreads();

    // ---------------- fc2 + residual -> sT (in place) ----------------
    {
        int o0 = q << 1;
        float4 a0, a1;
        gemm2x4<64>(sW, sH, o0, n0, a0, a1);
        float bb0 = sB[96 + o0], bb1 = sB[96 + o0 + 1];
        float4 t0 = *(float4*)&sT[o0 * 144 + n0];
        float4 t1 = *(float4*)&sT[(o0 + 1) * 144 + n0];
        a0.x += bb0 + t0.x; a0.y += bb0 + t0.y; a0.z += bb0 + t0.z; a0.w += bb0 + t0.w;
        a1.x += bb1 + t1.x; a1.y += bb1 + t1.y; a1.z += bb1 + t1.z; a1.w += bb1 + t1.w;
        *(float4*)&sT[o0 * 144 + n0]       = a0;
        *(float4*)&sT[(o0 + 1) * 144 + n0] = a1;
    }
    __syncthreads();

    // ---------------- FFN fc1 -> sS rows 0..31 ----------------
    {
        int o0 = q << 1;
        float4 a0, a1;
        gemm2x4<32>(sW + 2048, sT, o0, n0, a0, a1);
        float bb0 = sB[128 + o0], bb1 = sB[128 + o0 + 1];
        a0.x = gelu_exact(a0.x + bb0); a0.y = gelu_exact(a0.y + bb0);
        a0.z = gelu_exact(a0.z + bb0); a0.w = gelu_exact(a0.w + bb0);
        a1.x = gelu_exact(a1.x + bb1); a1.y = gelu_exact(a1.y + bb1);
        a1.z = gelu_exact(a1.z + bb1); a1.w = gelu_exact(a1.w + bb1);
        *(float4*)&sS[o0 * 144 + n0]       = a0;
        *(float4*)&sS[(o0 + 1) * 144 + n0] = a1;
    }
    __syncthreads();

    // ---------------- FFN fc2 + residual -> global ----------------
    {
        int o0 = q << 1;
        float4 a0, a1;
        gemm2x4<32>(sW + 3072, sS, o0, n0, a0, a1);
        float bb0 = sB[160 + o0], bb1 = sB[160 + o0 + 1];
        float4 t0 = *(float4*)&sT[o0 * 144 + n0];
        float4 t1 = *(float4*)&sT[(o0 + 1) * 144 + n0];
        a0.x += bb0 + t0.x; a0.y += bb0 + t0.y; a0.z += bb0 + t0.z; a0.w += bb0 + t0.w;
        a1.x += bb1 + t1.x; a1.y += bb1 + t1.y; a1.z += bb1 + t1.z; a1.w += bb1 + t1.w;
        float* go = gout + (size_t)b * 4608;
        *(float4*)&go[o0 * 144 + n0]       = a0;
        *(float4*)&go[(o0 + 1) * 144 + n0] = a1;
    }
}

extern "C" void kernel_launch(void* const* d_in, const int* in_sizes, int n_in,
                              void* d_out, int out_size) {
    (void)n_in; (void)out_size;
    int B = in_sizes[0] / (32 * 144);
    cudaFuncSetAttribute(gcn_kernel, cudaFuncAttributeMaxDynamicSharedMemorySize, SMEM_BYTES);
    gcn_kernel<<<B, TPB, SMEM_BYTES>>>(
        (const float*)d_in[0],  (const float*)d_in[1],  (const float*)d_in[2],
        (const float*)d_in[3],  (const float*)d_in[4],
        (const float*)d_in[5],  (const float*)d_in[6],
        (const float*)d_in[7],  (const float*)d_in[8],
        (const float*)d_in[9],  (const float*)d_in[10],
        (const float*)d_in[11], (const float*)d_in[12],
        (float*)d_out);
}

// round 5
// speedup vs baseline: 1.6529x; 1.6529x over previous
#include <cuda_runtime.h>
#include <math.h>

#define TPB 288
#define SMEM_FLOATS 27328
#define SMEM_BYTES (SMEM_FLOATS * 4)   // 109312 B -> 2 CTAs/SM

__device__ __forceinline__ float gelu_exact(float x) {
    return 0.5f * x * (1.0f + erff(x * 0.70710678118654752440f));
}

// cooperative transposed weight load: g[o][c] row-major -> s[c][OUT]
template<int OUT, int CIN>
__device__ __forceinline__ void load_wT(const float* __restrict__ g, float* __restrict__ s,
                                        int tid) {
    constexpr int NQ = OUT * CIN / 4;
    for (int i = tid; i < NQ; i += TPB) {
        float4 v = ((const float4*)g)[i];
        int o = i / (CIN / 4);
        int c = (i - o * (CIN / 4)) * 4;
        s[(c + 0) * OUT + o] = v.x;
        s[(c + 1) * OUT + o] = v.y;
        s[(c + 2) * OUT + o] = v.z;
        s[(c + 3) * OUT + o] = v.w;
    }
}

// 4-output x 4-n register tile; weights transposed [c][OUT]; c ascending (same numerics as R2)
template<int CIN, int OUT>
__device__ __forceinline__ void gemm4x4T(const float* __restrict__ Wt,
                                         const float* __restrict__ X,
                                         int o0, int n0, float4 a[4]) {
    a[0] = make_float4(0.f, 0.f, 0.f, 0.f);
    a[1] = a[0]; a[2] = a[0]; a[3] = a[0];
    #pragma unroll 8
    for (int c = 0; c < CIN; c++) {
        float4 w = *(const float4*)&Wt[c * OUT + o0];
        float4 v = *(const float4*)&X[c * 144 + n0];
        a[0].x = fmaf(w.x, v.x, a[0].x); a[0].y = fmaf(w.x, v.y, a[0].y);
        a[0].z = fmaf(w.x, v.z, a[0].z); a[0].w = fmaf(w.x, v.w, a[0].w);
        a[1].x = fmaf(w.y, v.x, a[1].x); a[1].y = fmaf(w.y, v.y, a[1].y);
        a[1].z = fmaf(w.y, v.z, a[1].z); a[1].w = fmaf(w.y, v.w, a[1].w);
        a[2].x = fmaf(w.z, v.x, a[2].x); a[2].y = fmaf(w.z, v.y, a[2].y);
        a[2].z = fmaf(w.z, v.z, a[2].z); a[2].w = fmaf(w.z, v.w, a[2].w);
        a[3].x = fmaf(w.w, v.x, a[3].x); a[3].y = fmaf(w.w, v.y, a[3].y);
        a[3].z = fmaf(w.w, v.z, a[3].z); a[3].w = fmaf(w.w, v.w, a[3].w);
    }
}

__global__ void __launch_bounds__(TPB, 2) gcn_kernel(
    const float* __restrict__ gin,  const float* __restrict__ gpos, const float* __restrict__ grel,
    const float* __restrict__ gW1,  const float* __restrict__ gb1,
    const float* __restrict__ gWc,  const float* __restrict__ gbc,
    const float* __restrict__ gW2,  const float* __restrict__ gb2,
    const float* __restrict__ gF1,  const float* __restrict__ gfb1,
    const float* __restrict__ gF2,  const float* __restrict__ gfb2,
    float* __restrict__ gout)
{
    extern __shared__ float sm[];
    float* sW = sm;                   // 4096: W1T -> WcT -> [W2T | F1T | F2T]
    float* sB = sW + 4096;            // 192 biases
    float* sT = sB + 192;             // 4608: tmp = in+pos; later grapher output  [c][n]
    float* sS = sT + 4608;            // 9216: stacked [2C][n]; later ffn hidden rows 0..31
    float* sU = sS + 9216;            // 9216: union { sXn + sSq + sIdx | sH conv out }
    float* sXn = sU;                  // [n][c] stride 36
    float* sSq = sU + 5184;           // 144
    int*   sIdx = (int*)(sU + 5376);  // 144*9
    float* sH = sU;                   // conv output [64][n]

    const int tid = threadIdx.x;
    const int b   = blockIdx.x;
    const int q   = tid / 36;         // 0..7
    const int r   = tid - q * 36;     // 0..35
    const int n0  = r << 2;

    // ---------------- stage 0: W1T + biases + input(+pos) ----------------
    load_wT<32, 32>(gW1, sW, tid);
    if (tid < 32)       sB[tid] = gb1[tid];
    else if (tid < 96)  sB[tid] = gbc[tid - 32];
    else if (tid < 128) sB[tid] = gb2[tid - 96];
    else if (tid < 160) sB[tid] = gfb1[tid - 128];
    else if (tid < 192) sB[tid] = gfb2[tid - 160];
    {
        const float4* gi4 = (const float4*)(gin + (size_t)b * 4608);
        const float4* gp4 = (const float4*)gpos;
        for (int i = tid; i < 1152; i += TPB) {
            float4 a = gi4[i], p = gp4[i];
            a.x += p.x; a.y += p.y; a.z += p.z; a.w += p.w;
            ((float4*)sT)[i] = a;
        }
    }
    __syncthreads();

    // ---------------- fc1: xf = W1 @ tmp + b1 -> sS even rows ----------------
    {
        int o0 = q << 2;
        float4 a[4];
        gemm4x4T<32, 32>(sW, sT, o0, n0, a);
        #pragma unroll
        for (int j = 0; j < 4; j++) {
            float bb = sB[o0 + j];
            a[j].x += bb; a[j].y += bb; a[j].z += bb; a[j].w += bb;
            *(float4*)&sS[(2 * (o0 + j)) * 144 + n0] = a[j];
        }
    }
    __syncthreads();

    // ---------------- normalize (tid<144) in parallel with WcT load ----------------
    if (tid < 144) {
        float v[32]; float s = 0.f;
        #pragma unroll
        for (int c = 0; c < 32; c++) { float x = sS[(2 * c) * 144 + tid]; v[c] = x; s = fmaf(x, x, s); }
        float nrm = fmaxf(sqrtf(s), 1e-12f);
        float sq = 0.f;
        #pragma unroll
        for (int c = 0; c < 32; c++) { float xn = v[c] / nrm; sXn[tid * 36 + c] = xn; sq = fmaf(xn, xn, sq); }
        sSq[tid] = sq;
    } else {
        // WcT: 64x64 -> [c][64]
        constexpr int NQ = 64 * 64 / 4;
        for (int i = tid - 144; i < NQ; i += TPB - 144) {
            float4 v = ((const float4*)gWc)[i];
            int o = i / 16;
            int c = (i - o * 16) * 4;
            sW[(c + 0) * 64 + o] = v.x;
            sW[(c + 1) * 64 + o] = v.y;
            sW[(c + 2) * 64 + o] = v.z;
            sW[(c + 3) * 64 + o] = v.w;
        }
    }
    __syncthreads();

    // ---------------- pairwise dist + top-9 (2-way m split, shuffle merge) ----------------
    {
        const int row  = tid >> 1;       // 0..143
        const int part = tid & 1;
        const float4* xr4 = (const float4*)&sXn[row * 36];
        float4 v4[8];
        #pragma unroll
        for (int i = 0; i < 8; i++) v4[i] = xr4[i];
        const float sqn = sSq[row];
        float bd[9]; int bi[9];
        #pragma unroll
        for (int k = 0; k < 9; k++) { bd[k] = 3.0e38f; bi[k] = 0; }
        int m = part * 72;
        const float* relp = grel + (size_t)m * 144 + row;   // symmetric table -> coalesced
        for (int mm = 0; mm < 72; mm++, m++, relp += 144) {
            const float4* xm = (const float4*)&sXn[m * 36];
            float4 a;
            float d0, d1, d2, d3;
            a = xm[0];
            d0 = v4[0].x * a.x; d1 = v4[0].y * a.y; d2 = v4[0].z * a.z; d3 = v4[0].w * a.w;
            #pragma unroll
            for (int c4 = 1; c4 < 8; c4++) {
                a = xm[c4];
                d0 = fmaf(v4[c4].x, a.x, d0); d1 = fmaf(v4[c4].y, a.y, d1);
                d2 = fmaf(v4[c4].z, a.z, d2); d3 = fmaf(v4[c4].w, a.w, d3);
            }
            float dot = (d0 + d1) + (d2 + d3);
            float d = (sqn - 2.0f * dot) + sSq[m] + *relp;
            if (d < bd[8]) {                     // strict-less: ties keep lower index
                bd[8] = d; bi[8] = m;
                #pragma unroll
                for (int j = 8; j > 0; --j) {
                    if (bd[j] < bd[j-1]) {
                        float td = bd[j]; bd[j] = bd[j-1]; bd[j-1] = td;
                        int   ti = bi[j]; bi[j] = bi[j-1]; bi[j-1] = ti;
                    }
                }
            }
        }
        // merge part 1 into part 0 (ascending m preserves tie rule)
        #pragma unroll
        for (int k = 0; k < 9; k++) {
            float d  = __shfl_sync(0xFFFFFFFFu, bd[k], 1, 2);
            int   mi = __shfl_sync(0xFFFFFFFFu, bi[k], 1, 2);
            if (part == 0 && d < bd[8]) {
                bd[8] = d; bi[8] = mi;
                #pragma unroll
                for (int j = 8; j > 0; --j) {
                    if (bd[j] < bd[j-1]) {
                        float td = bd[j]; bd[j] = bd[j-1]; bd[j-1] = td;
                        int   ti = bi[j]; bi[j] = bi[j-1]; bi[j-1] = ti;
                    }
                }
            }
        }
        if (part == 0) {
            #pragma unroll
            for (int k = 0; k < 9; k++) sIdx[row * 9 + k] = bi[k];
        }
    }
    __syncthreads();

    // ---------------- MRConv: thread = (n, 16-channel group); idx loaded once ----------------
    {
        const int n2 = tid % 144;
        const int g  = tid / 144;          // 0..1
        int idx9[9];
        #pragma unroll
        for (int k = 0; k < 9; k++) idx9[k] = sIdx[n2 * 9 + k];
        #pragma unroll
        for (int cc = 0; cc < 16; cc++) {
            int c = g * 16 + cc;
            const float* xrow = &sS[(2 * c) * 144];
            float xi = xrow[n2];
            float mx = -3.0e38f;
            #pragma unroll
            for (int k = 0; k < 9; k++) mx = fmaxf(mx, xrow[idx9[k]] - xi);
            sS[(2 * c + 1) * 144 + n2] = mx;
        }
    }
    __syncthreads();

    // ---------------- conv: hc = gelu(WcT @ stacked + bc), 8o x 4n -> sH ----------------
    {
        const int o0 = q << 3;             // 0..56
        float4 A[8];
        #pragma unroll
        for (int j = 0; j < 8; j++) A[j] = make_float4(0.f, 0.f, 0.f, 0.f);
        #pragma unroll 8
        for (int c = 0; c < 64; c++) {
            float4 w0 = *(const float4*)&sW[c * 64 + o0];
            float4 w1 = *(const float4*)&sW[c * 64 + o0 + 4];
            float4 v  = *(const float4*)&sS[c * 144 + n0];
            A[0].x = fmaf(w0.x, v.x, A[0].x); A[0].y = fmaf(w0.x, v.y, A[0].y);
            A[0].z = fmaf(w0.x, v.z, A[0].z); A[0].w = fmaf(w0.x, v.w, A[0].w);
            A[1].x = fmaf(w0.y, v.x, A[1].x); A[1].y = fmaf(w0.y, v.y, A[1].y);
            A[1].z = fmaf(w0.y, v.z, A[1].z); A[1].w = fmaf(w0.y, v.w, A[1].w);
            A[2].x = fmaf(w0.z, v.x, A[2].x); A[2].y = fmaf(w0.z, v.y, A[2].y);
            A[2].z = fmaf(w0.z, v.z, A[2].z); A[2].w = fmaf(w0.z, v.w, A[2].w);
            A[3].x = fmaf(w0.w, v.x, A[3].x); A[3].y = fmaf(w0.w, v.y, A[3].y);
            A[3].z = fmaf(w0.w, v.z, A[3].z); A[3].w = fmaf(w0.w, v.w, A[3].w);
            A[4].x = fmaf(w1.x, v.x, A[4].x); A[4].y = fmaf(w1.x, v.y, A[4].y);
            A[4].z = fmaf(w1.x, v.z, A[4].z); A[4].w = fmaf(w1.x, v.w, A[4].w);
            A[5].x = fmaf(w1.y, v.x, A[5].x); A[5].y = fmaf(w1.y, v.y, A[5].y);
            A[5].z = fmaf(w1.y, v.z, A[5].z); A[5].w = fmaf(w1.y, v.w, A[5].w);
            A[6].x = fmaf(w1.z, v.x, A[6].x); A[6].y = fmaf(w1.z, v.y, A[6].y);
            A[6].z = fmaf(w1.z, v.z, A[6].z); A[6].w = fmaf(w1.z, v.w, A[6].w);
            A[7].x = fmaf(w1.w, v.x, A[7].x); A[7].y = fmaf(w1.w, v.y, A[7].y);
            A[7].z = fmaf(w1.w, v.z, A[7].z); A[7].w = fmaf(w1.w, v.w, A[7].w);
        }
        #pragma unroll
        for (int j = 0; j < 8; j++) {
            float bb = sB[32 + o0 + j];
            A[j].x = gelu_exact(A[j].x + bb); A[j].y = gelu_exact(A[j].y + bb);
            A[j].z = gelu_exact(A[j].z + bb); A[j].w = gelu_exact(A[j].w + bb);
            *(float4*)&sH[(o0 + j) * 144 + n0] = A[j];
        }
    }
    __syncthreads();

    // ---------------- reload weights: [W2T | F1T | F2T] ----------------
    load_wT<32, 64>(gW2, sW, tid);
    load_wT<32, 32>(gF1, sW + 2048, tid);
    load_wT<32, 32>(gF2, sW + 3072, tid);
    __syncthreads();

    // ---------------- fc2 + residual -> sT (in place) ----------------
    {
        int o0 = q << 2;
        float4 a[4];
        gemm4x4T<64, 32>(sW, sH, o0, n0, a);
        #pragma unroll
        for (int j = 0; j < 4; j++) {
            float bb = sB[96 + o0 + j];
            float4 t = *(float4*)&sT[(o0 + j) * 144 + n0];
            a[j].x += bb + t.x; a[j].y += bb + t.y; a[j].z += bb + t.z; a[j].w += bb + t.w;
            *(float4*)&sT[(o0 + j) * 144 + n0] = a[j];
        }
    }
    __syncthreads();

    // ---------------- FFN fc1 -> sS rows 0..31 ----------------
    {
        int o0 = q << 2;
        float4 a[4];
        gemm4x4T<32, 32>(sW + 2048, sT, o0, n0, a);
        #pragma unroll
        for (int j = 0; j < 4; j++) {
            float bb = sB[128 + o0 + j];
            a[j].x = gelu_exact(a[j].x + bb); a[j].y = gelu_exact(a[j].y + bb);
            a[j].z = gelu_exact(a[j].z + bb); a[j].w = gelu_exact(a[j].w + bb);
            *(float4*)&sS[(o0 + j) * 144 + n0] = a[j];
        }
    }
    __syncthreads();

    // ---------------- FFN fc2 + residual -> global ----------------
    {
        int o0 = q << 2;
        float4 a[4];
        gemm4x4T<32, 32>(sW + 3072, sS, o0, n0, a);
        float* go = gout + (size_t)b * 4608;
        #pragma unroll
        for (int j = 0; j < 4; j++) {
            float bb = sB[160 + o0 + j];
            float4 t = *(float4*)&sT[(o0 + j) * 144 + n0];
            a[j].x += bb + t.x; a[j].y += bb + t.y; a[j].z += bb + t.z; a[j].w += bb + t.w;
            *(float4*)&go[(o0 + j) * 144 + n0] = a[j];
        }
    }
}

extern "C" void kernel_launch(void* const* d_in, const int* in_sizes, int n_in,
                              void* d_out, int out_size) {
    (void)n_in; (void)out_size;
    int B = in_sizes[0] / (32 * 144);
    cudaFuncSetAttribute(gcn_kernel, cudaFuncAttributeMaxDynamicSharedMemorySize, SMEM_BYTES);
    gcn_kernel<<<B, TPB, SMEM_BYTES>>>(
        (const float*)d_in[0],  (const float*)d_in[1],  (const float*)d_in[2],
        (const float*)d_in[3],  (const float*)d_in[4],
        (const float*)d_in[5],  (const float*)d_in[6],
        (const float*)d_in[7],  (const float*)d_in[8],
        (const float*)d_in[9],  (const float*)d_in[10],
        (const float*)d_in[11], (const float*)d_in[12],
        (float*)d_out);
}

// round 7
// speedup vs baseline: 1.7691x; 1.0703x over previous
#include <cuda_runtime.h>
#include <math.h>

#define TPB 288
#define SMEM_FLOATS 27328
#define SMEM_BYTES (SMEM_FLOATS * 4)   // 109312 B -> 2 CTAs/SM

typedef unsigned long long ull;

__device__ __forceinline__ float gelu_exact(float x) {
    return 0.5f * x * (1.0f + erff(x * 0.70710678118654752440f));
}

__device__ __forceinline__ ull mul2(ull a, ull b) {
    ull d; asm("mul.rn.f32x2 %0, %1, %2;" : "=l"(d) : "l"(a), "l"(b)); return d;
}
__device__ __forceinline__ ull fma2(ull a, ull b, ull c) {
    ull d; asm("fma.rn.f32x2 %0, %1, %2, %3;" : "=l"(d) : "l"(a), "l"(b), "l"(c)); return d;
}
__device__ __forceinline__ void unpack2(ull v, float& lo, float& hi) {
    unsigned int l, h;
    asm("mov.b64 {%0, %1}, %2;" : "=r"(l), "=r"(h) : "l"(v));
    lo = __uint_as_float(l); hi = __uint_as_float(h);
}

// cooperative transposed weight load: g[o][c] row-major -> s[c][OUT]
template<int OUT, int CIN>
__device__ __forceinline__ void load_wT(const float* __restrict__ g, float* __restrict__ s,
                                        int tid) {
    constexpr int NQ = OUT * CIN / 4;
    for (int i = tid; i < NQ; i += TPB) {
        float4 v = ((const float4*)g)[i];
        int o = i / (CIN / 4);
        int c = (i - o * (CIN / 4)) * 4;
        s[(c + 0) * OUT + o] = v.x;
        s[(c + 1) * OUT + o] = v.y;
        s[(c + 2) * OUT + o] = v.z;
        s[(c + 3) * OUT + o] = v.w;
    }
}

// 4-output x 4-n register tile; weights transposed [c][OUT]; c ascending (R2 numerics)
template<int CIN, int OUT>
__device__ __forceinline__ void gemm4x4T(const float* __restrict__ Wt,
                                         const float* __restrict__ X,
                                         int o0, int n0, float4 a[4]) {
    a[0] = make_float4(0.f, 0.f, 0.f, 0.f);
    a[1] = a[0]; a[2] = a[0]; a[3] = a[0];
    #pragma unroll 8
    for (int c = 0; c < CIN; c++) {
        float4 w = *(const float4*)&Wt[c * OUT + o0];
        float4 v = *(const float4*)&X[c * 144 + n0];
        a[0].x = fmaf(w.x, v.x, a[0].x); a[0].y = fmaf(w.x, v.y, a[0].y);
        a[0].z = fmaf(w.x, v.z, a[0].z); a[0].w = fmaf(w.x, v.w, a[0].w);
        a[1].x = fmaf(w.y, v.x, a[1].x); a[1].y = fmaf(w.y, v.y, a[1].y);
        a[1].z = fmaf(w.y, v.z, a[1].z); a[1].w = fmaf(w.y, v.w, a[1].w);
        a[2].x = fmaf(w.z, v.x, a[2].x); a[2].y = fmaf(w.z, v.y, a[2].y);
        a[2].z = fmaf(w.z, v.z, a[2].z); a[2].w = fmaf(w.z, v.w, a[2].w);
        a[3].x = fmaf(w.w, v.x, a[3].x); a[3].y = fmaf(w.w, v.y, a[3].y);
        a[3].z = fmaf(w.w, v.z, a[3].z); a[3].w = fmaf(w.w, v.w, a[3].w);
    }
}

__global__ void __launch_bounds__(TPB, 2) gcn_kernel(
    const float* __restrict__ gin,  const float* __restrict__ gpos, const float* __restrict__ grel,
    const float* __restrict__ gW1,  const float* __restrict__ gb1,
    const float* __restrict__ gWc,  const float* __restrict__ gbc,
    const float* __restrict__ gW2,  const float* __restrict__ gb2,
    const float* __restrict__ gF1,  const float* __restrict__ gfb1,
    const float* __restrict__ gF2,  const float* __restrict__ gfb2,
    float* __restrict__ gout)
{
    extern __shared__ float sm[];
    float* sW = sm;                   // 4096: W1T -> WcT -> [W2T | F1T | F2T]
    float* sB = sW + 4096;            // 192 biases
    float* sT = sB + 192;             // 4608: tmp = in+pos; later grapher output [c][n]
    float* sS = sT + 4608;            // 9216: stacked [2C][n]; later ffn hidden rows 0..31
    float* sU = sS + 9216;            // 9216: union { sXn/sSq/sIdx/merge | sH conv out }
    float* sXn = sU;                  // [n][c] stride 36
    float* sSq = sU + 5184;           // 144
    int*   sIdx = (int*)(sU + 5376);  // 144*9 ints -> ends at sU+5700
    float* sMrgD = sU + 5704;         // 144*9 floats (part-1 staging)
    int*   sMrgI = (int*)(sU + 7000); // 144*9 ints   -> ends at sU+8296 < 9216
    float* sH = sU;                   // conv output [64][n]

    const int tid = threadIdx.x;
    const int b   = blockIdx.x;
    const int q   = tid / 36;         // 0..7
    const int r   = tid - q * 36;     // 0..35
    const int n0  = r << 2;

    // ---------------- stage 0: W1T + biases + input(+pos) ----------------
    load_wT<32, 32>(gW1, sW, tid);
    if (tid < 32)       sB[tid] = gb1[tid];
    else if (tid < 96)  sB[tid] = gbc[tid - 32];
    else if (tid < 128) sB[tid] = gb2[tid - 96];
    else if (tid < 160) sB[tid] = gfb1[tid - 128];
    else if (tid < 192) sB[tid] = gfb2[tid - 160];
    {
        const float4* gi4 = (const float4*)(gin + (size_t)b * 4608);
        const float4* gp4 = (const float4*)gpos;
        for (int i = tid; i < 1152; i += TPB) {
            float4 a = gi4[i], p = gp4[i];
            a.x += p.x; a.y += p.y; a.z += p.z; a.w += p.w;
            ((float4*)sT)[i] = a;
        }
    }
    __syncthreads();

    // ---------------- fc1: xf = W1 @ tmp + b1 -> sS even rows ----------------
    {
        int o0 = q << 2;
        float4 a[4];
        gemm4x4T<32, 32>(sW, sT, o0, n0, a);
        #pragma unroll
        for (int j = 0; j < 4; j++) {
            float bb = sB[o0 + j];
            a[j].x += bb; a[j].y += bb; a[j].z += bb; a[j].w += bb;
            *(float4*)&sS[(2 * (o0 + j)) * 144 + n0] = a[j];
        }
    }
    __syncthreads();

    // ---------------- normalize (tid<144) in parallel with WcT load ----------------
    if (tid < 144) {
        float v[32]; float s = 0.f;
        #pragma unroll
        for (int c = 0; c < 32; c++) { float x = sS[(2 * c) * 144 + tid]; v[c] = x; s = fmaf(x, x, s); }
        float nrm = fmaxf(sqrtf(s), 1e-12f);
        float sq = 0.f;
        #pragma unroll
        for (int c = 0; c < 32; c++) { float xn = v[c] / nrm; sXn[tid * 36 + c] = xn; sq = fmaf(xn, xn, sq); }
        sSq[tid] = sq;
    } else {
        // WcT: 64x64 -> [c][64]
        constexpr int NQ = 64 * 64 / 4;
        for (int i = tid - 144; i < NQ; i += TPB - 144) {
            float4 v = ((const float4*)gWc)[i];
            int o = i / 16;
            int c = (i - o * 16) * 4;
            sW[(c + 0) * 64 + o] = v.x;
            sW[(c + 1) * 64 + o] = v.y;
            sW[(c + 2) * 64 + o] = v.z;
            sW[(c + 3) * 64 + o] = v.w;
        }
    }
    __syncthreads();

    // ---------------- pairwise dist + top-9 ----------------
    // part-major: warp processes one m at a time -> xm LDS is single-address broadcast,
    // grel coalesced + prefetched. FFMA2 packs the 4 R2 accumulator chains into 2:
    // d01 = pairs (4i,4i+1), d23 = pairs (4i+2,4i+3) -> lanes reproduce R2's d0..d3 exactly.
    {
        const int row  = (tid < 144) ? tid : tid - 144;
        const int part = (tid < 144) ? 0 : 1;
        ull vv[16];                              // all 32 channels as 16 packed pairs
        {
            const ulonglong2* xr2 = (const ulonglong2*)&sXn[row * 36];
            #pragma unroll
            for (int i = 0; i < 8; i++) { ulonglong2 t = xr2[i]; vv[2*i] = t.x; vv[2*i+1] = t.y; }
        }
        const float sqn = sSq[row];
        float bd[9]; int bi[9];
        #pragma unroll
        for (int k = 0; k < 9; k++) { bd[k] = 3.0e38f; bi[k] = 0; }
        const int m0 = part * 72;
        const float* relp = grel + (size_t)m0 * 144 + row;
        float relv = *relp; relp += 144;
        for (int mm = 0; mm < 72; mm++) {
            const int m = m0 + mm;
            float rel_next = (mm < 71) ? *relp : 0.f; relp += 144;   // prefetch
            const ulonglong2* xm2 = (const ulonglong2*)&sXn[m * 36];
            ulonglong2 t = xm2[0];
            ull d01 = mul2(vv[0], t.x);
            ull d23 = mul2(vv[1], t.y);
            #pragma unroll
            for (int i = 1; i < 8; i++) {
                t = xm2[i];
                d01 = fma2(vv[2*i],   t.x, d01);
                d23 = fma2(vv[2*i+1], t.y, d23);
            }
            float d0, d1, d2, d3;
            unpack2(d01, d0, d1);
            unpack2(d23, d2, d3);
            float dot = (d0 + d1) + (d2 + d3);
            float d = (sqn - 2.0f * dot) + sSq[m] + relv;
            relv = rel_next;
            if (d < bd[8]) {                     // strict-less: ties keep lower index
                bd[8] = d; bi[8] = m;
                #pragma unroll
                for (int j = 8; j > 0; --j) {
                    if (bd[j] < bd[j-1]) {
                        float td = bd[j]; bd[j] = bd[j-1]; bd[j-1] = td;
                        int   ti = bi[j]; bi[j] = bi[j-1]; bi[j-1] = ti;
                    }
                }
            }
        }
        if (part == 1) {                          // stage part-1 lists
            int base = row * 9;
            #pragma unroll
            for (int k = 0; k < 9; k++) { sMrgD[base + k] = bd[k]; sMrgI[base + k] = bi[k]; }
        }
        __syncthreads();
        if (part == 0) {                          // merge (ascending m preserves tie rule)
            int base = row * 9;
            #pragma unroll
            for (int k = 0; k < 9; k++) {
                float d = sMrgD[base + k]; int mi = sMrgI[base + k];
                if (d < bd[8]) {
                    bd[8] = d; bi[8] = mi;
                    #pragma unroll
                    for (int j = 8; j > 0; --j) {
                        if (bd[j] < bd[j-1]) {
                            float td = bd[j]; bd[j] = bd[j-1]; bd[j-1] = td;
                            int   ti = bi[j]; bi[j] = bi[j-1]; bi[j-1] = ti;
                        }
                    }
                }
            }
            #pragma unroll
            for (int k = 0; k < 9; k++) sIdx[row * 9 + k] = bi[k];
        }
    }
    __syncthreads();

    // ---------------- MRConv: max over gathers, then subtract (bit-identical) ----------------
    {
        const int n2 = tid % 144;
        const int g  = tid / 144;          // 0..1 -> channels g*16..g*16+15
        int idx9[9];
        #pragma unroll
        for (int k = 0; k < 9; k++) idx9[k] = sIdx[n2 * 9 + k];
        #pragma unroll
        for (int cc = 0; cc < 16; cc++) {
            int c = g * 16 + cc;
            const float* xrow = &sS[(2 * c) * 144];
            float mx = xrow[idx9[0]];
            #pragma unroll
            for (int k = 1; k < 9; k++) mx = fmaxf(mx, xrow[idx9[k]]);
            sS[(2 * c + 1) * 144 + n2] = mx - xrow[n2];
        }
    }
    __syncthreads();

    // ---------------- conv: hc = gelu(WcT @ stacked + bc), 8o x 4n -> sH ----------------
    {
        const int o0 = q << 3;             // 0..56
        float4 A[8];
        #pragma unroll
        for (int j = 0; j < 8; j++) A[j] = make_float4(0.f, 0.f, 0.f, 0.f);
        #pragma unroll 8
        for (int c = 0; c < 64; c++) {
            float4 w0 = *(const float4*)&sW[c * 64 + o0];
            float4 w1 = *(const float4*)&sW[c * 64 + o0 + 4];
            float4 v  = *(const float4*)&sS[c * 144 + n0];
            A[0].x = fmaf(w0.x, v.x, A[0].x); A[0].y = fmaf(w0.x, v.y, A[0].y);
            A[0].z = fmaf(w0.x, v.z, A[0].z); A[0].w = fmaf(w0.x, v.w, A[0].w);
            A[1].x = fmaf(w0.y, v.x, A[1].x); A[1].y = fmaf(w0.y, v.y, A[1].y);
            A[1].z = fmaf(w0.y, v.z, A[1].z); A[1].w = fmaf(w0.y, v.w, A[1].w);
            A[2].x = fmaf(w0.z, v.x, A[2].x); A[2].y = fmaf(w0.z, v.y, A[2].y);
            A[2].z = fmaf(w0.z, v.z, A[2].z); A[2].w = fmaf(w0.z, v.w, A[2].w);
            A[3].x = fmaf(w0.w, v.x, A[3].x); A[3].y = fmaf(w0.w, v.y, A[3].y);
            A[3].z = fmaf(w0.w, v.z, A[3].z); A[3].w = fmaf(w0.w, v.w, A[3].w);
            A[4].x = fmaf(w1.x, v.x, A[4].x); A[4].y = fmaf(w1.x, v.y, A[4].y);
            A[4].z = fmaf(w1.x, v.z, A[4].z); A[4].w = fmaf(w1.x, v.w, A[4].w);
            A[5].x = fmaf(w1.y, v.x, A[5].x); A[5].y = fmaf(w1.y, v.y, A[5].y);
            A[5].z = fmaf(w1.y, v.z, A[5].z); A[5].w = fmaf(w1.y, v.w, A[5].w);
            A[6].x = fmaf(w1.z, v.x, A[6].x); A[6].y = fmaf(w1.z, v.y, A[6].y);
            A[6].z = fmaf(w1.z, v.z, A[6].z); A[6].w = fmaf(w1.z, v.w, A[6].w);
            A[7].x = fmaf(w1.w, v.x, A[7].x); A[7].y = fmaf(w1.w, v.y, A[7].y);
            A[7].z = fmaf(w1.w, v.z, A[7].z); A[7].w = fmaf(w1.w, v.w, A[7].w);
        }
        #pragma unroll
        for (int j = 0; j < 8; j++) {
            float bb = sB[32 + o0 + j];
            A[j].x = gelu_exact(A[j].x + bb); A[j].y = gelu_exact(A[j].y + bb);
            A[j].z = gelu_exact(A[j].z + bb); A[j].w = gelu_exact(A[j].w + bb);
            *(float4*)&sH[(o0 + j) * 144 + n0] = A[j];
        }
    }
    __syncthreads();

    // ---------------- reload weights: [W2T | F1T | F2T] ----------------
    load_wT<32, 64>(gW2, sW, tid);
    load_wT<32, 32>(gF1, sW + 2048, tid);
    load_wT<32, 32>(gF2, sW + 3072, tid);
    __syncthreads();

    // ---------------- fc2 + residual -> sT (in place) ----------------
    {
        int o0 = q << 2;
        float4 a[4];
        gemm4x4T<64, 32>(sW, sH, o0, n0, a);
        #pragma unroll
        for (int j = 0; j < 4; j++) {
            float bb = sB[96 + o0 + j];
            float4 t = *(float4*)&sT[(o0 + j) * 144 + n0];
            a[j].x += bb + t.x; a[j].y += bb + t.y; a[j].z += bb + t.z; a[j].w += bb + t.w;
            *(float4*)&sT[(o0 + j) * 144 + n0] = a[j];
        }
    }
    __syncthreads();

    // ---------------- FFN fc1 -> sS rows 0..31 ----------------
    {
        int o0 = q << 2;
        float4 a[4];
        gemm4x4T<32, 32>(sW + 2048, sT, o0, n0, a);
        #pragma unroll
        for (int j = 0; j < 4; j++) {
            float bb = sB[128 + o0 + j];
            a[j].x = gelu_exact(a[j].x + bb); a[j].y = gelu_exact(a[j].y + bb);
            a[j].z = gelu_exact(a[j].z + bb); a[j].w = gelu_exact(a[j].w + bb);
            *(float4*)&sS[(o0 + j) * 144 + n0] = a[j];
        }
    }
    __syncthreads();

    // ---------------- FFN fc2 + residual -> global ----------------
    {
        int o0 = q << 2;
        float4 a[4];
        gemm4x4T<32, 32>(sW + 3072, sS, o0, n0, a);
        float* go = gout + (size_t)b * 4608;
        #pragma unroll
        for (int j = 0; j < 4; j++) {
            float bb = sB[160 + o0 + j];
            float4 t = *(float4*)&sT[(o0 + j) * 144 + n0];
            a[j].x += bb + t.x; a[j].y += bb + t.y; a[j].z += bb + t.z; a[j].w += bb + t.w;
            *(float4*)&go[(o0 + j) * 144 + n0] = a[j];
        }
    }
}

extern "C" void kernel_launch(void* const* d_in, const int* in_sizes, int n_in,
                              void* d_out, int out_size) {
    (void)n_in; (void)out_size;
    int B = in_sizes[0] / (32 * 144);
    cudaFuncSetAttribute(gcn_kernel, cudaFuncAttributeMaxDynamicSharedMemorySize, SMEM_BYTES);
    gcn_kernel<<<B, TPB, SMEM_BYTES>>>(
        (const float*)d_in[0],  (const float*)d_in[1],  (const float*)d_in[2],
        (const float*)d_in[3],  (const float*)d_in[4],
        (const float*)d_in[5],  (const float*)d_in[6],
        (const float*)d_in[7],  (const float*)d_in[8],
        (const float*)d_in[9],  (const float*)d_in[10],
        (const float*)d_in[11], (const float*)d_in[12],
        (float*)d_out);
}

// round 8
// speedup vs baseline: 1.7835x; 1.0081x over previous
#include <cuda_runtime.h>
#include <math.h>

#define TPB 288
#define SMEM_FLOATS 27328
#define SMEM_BYTES (SMEM_FLOATS * 4)   // 109312 B -> 2 CTAs/SM

typedef unsigned long long ull;

__device__ __forceinline__ float gelu_exact(float x) {
    return 0.5f * x * (1.0f + erff(x * 0.70710678118654752440f));
}

__device__ __forceinline__ ull mul2(ull a, ull b) {
    ull d; asm("mul.rn.f32x2 %0, %1, %2;" : "=l"(d) : "l"(a), "l"(b)); return d;
}
__device__ __forceinline__ ull fma2(ull a, ull b, ull c) {
    ull d; asm("fma.rn.f32x2 %0, %1, %2, %3;" : "=l"(d) : "l"(a), "l"(b), "l"(c)); return d;
}
__device__ __forceinline__ void unpack2(ull v, float& lo, float& hi) {
    unsigned int l, h;
    asm("mov.b64 {%0, %1}, %2;" : "=r"(l), "=r"(h) : "l"(v));
    lo = __uint_as_float(l); hi = __uint_as_float(h);
}
__device__ __forceinline__ ull pack2(float x) {
    ull d; asm("mov.b64 %0, {%1, %1};" : "=l"(d) : "f"(x)); return d;
}

// cooperative transposed weight load: g[o][c] row-major -> s[c][OUT]
template<int OUT, int CIN>
__device__ __forceinline__ void load_wT(const float* __restrict__ g, float* __restrict__ s,
                                        int tid) {
    constexpr int NQ = OUT * CIN / 4;
    for (int i = tid; i < NQ; i += TPB) {
        float4 v = ((const float4*)g)[i];
        int o = i / (CIN / 4);
        int c = (i - o * (CIN / 4)) * 4;
        s[(c + 0) * OUT + o] = v.x;
        s[(c + 1) * OUT + o] = v.y;
        s[(c + 2) * OUT + o] = v.z;
        s[(c + 3) * OUT + o] = v.w;
    }
}

// 4-output x 4-n register tile; weights transposed [c][OUT]; c ascending (R2 numerics)
template<int CIN, int OUT>
__device__ __forceinline__ void gemm4x4T(const float* __restrict__ Wt,
                                         const float* __restrict__ X,
                                         int o0, int n0, float4 a[4]) {
    a[0] = make_float4(0.f, 0.f, 0.f, 0.f);
    a[1] = a[0]; a[2] = a[0]; a[3] = a[0];
    #pragma unroll 8
    for (int c = 0; c < CIN; c++) {
        float4 w = *(const float4*)&Wt[c * OUT + o0];
        float4 v = *(const float4*)&X[c * 144 + n0];
        a[0].x = fmaf(w.x, v.x, a[0].x); a[0].y = fmaf(w.x, v.y, a[0].y);
        a[0].z = fmaf(w.x, v.z, a[0].z); a[0].w = fmaf(w.x, v.w, a[0].w);
        a[1].x = fmaf(w.y, v.x, a[1].x); a[1].y = fmaf(w.y, v.y, a[1].y);
        a[1].z = fmaf(w.y, v.z, a[1].z); a[1].w = fmaf(w.y, v.w, a[1].w);
        a[2].x = fmaf(w.z, v.x, a[2].x); a[2].y = fmaf(w.z, v.y, a[2].y);
        a[2].z = fmaf(w.z, v.z, a[2].z); a[2].w = fmaf(w.z, v.w, a[2].w);
        a[3].x = fmaf(w.w, v.x, a[3].x); a[3].y = fmaf(w.w, v.y, a[3].y);
        a[3].z = fmaf(w.w, v.z, a[3].z); a[3].w = fmaf(w.w, v.w, a[3].w);
    }
}

__global__ void __launch_bounds__(TPB, 2) gcn_kernel(
    const float* __restrict__ gin,  const float* __restrict__ gpos, const float* __restrict__ grel,
    const float* __restrict__ gW1,  const float* __restrict__ gb1,
    const float* __restrict__ gWc,  const float* __restrict__ gbc,
    const float* __restrict__ gW2,  const float* __restrict__ gb2,
    const float* __restrict__ gF1,  const float* __restrict__ gfb1,
    const float* __restrict__ gF2,  const float* __restrict__ gfb2,
    float* __restrict__ gout)
{
    extern __shared__ float sm[];
    float* sW = sm;                   // 4096: W1T -> WcT -> [W2T | F1T | F2T]
    float* sB = sW + 4096;            // 192 biases
    float* sT = sB + 192;             // 4608: tmp = in+pos; later grapher output [c][n]
    float* sS = sT + 4608;            // 9216: stacked [2C][n]; later ffn hidden rows 0..31
    float* sU = sS + 9216;            // 9216: union { sXn/sSq/sIdx/merge | sH conv out }
    float* sXn = sU;                  // [n][c] stride 36
    float* sSq = sU + 5184;           // 144
    int*   sIdx = (int*)(sU + 5376);  // 144*9 ints -> ends at sU+5700
    float* sMrgD = sU + 5704;         // 144*9 floats (part-1 staging)
    int*   sMrgI = (int*)(sU + 7000); // 144*9 ints   -> ends at sU+8296 < 9216
    float* sH = sU;                   // conv output [64][n]

    const int tid = threadIdx.x;
    const int b   = blockIdx.x;
    const int q   = tid / 36;         // 0..7
    const int r   = tid - q * 36;     // 0..35
    const int n0  = r << 2;

    // ---------------- stage 0: W1T + biases + input(+pos) ----------------
    load_wT<32, 32>(gW1, sW, tid);
    if (tid < 32)       sB[tid] = gb1[tid];
    else if (tid < 96)  sB[tid] = gbc[tid - 32];
    else if (tid < 128) sB[tid] = gb2[tid - 96];
    else if (tid < 160) sB[tid] = gfb1[tid - 128];
    else if (tid < 192) sB[tid] = gfb2[tid - 160];
    {
        const float4* gi4 = (const float4*)(gin + (size_t)b * 4608);
        const float4* gp4 = (const float4*)gpos;
        for (int i = tid; i < 1152; i += TPB) {
            float4 a = gi4[i], p = gp4[i];
            a.x += p.x; a.y += p.y; a.z += p.z; a.w += p.w;
            ((float4*)sT)[i] = a;
        }
    }
    __syncthreads();

    // ---------------- fc1: xf = W1 @ tmp + b1 -> sS even rows ----------------
    {
        int o0 = q << 2;
        float4 a[4];
        gemm4x4T<32, 32>(sW, sT, o0, n0, a);
        #pragma unroll
        for (int j = 0; j < 4; j++) {
            float bb = sB[o0 + j];
            a[j].x += bb; a[j].y += bb; a[j].z += bb; a[j].w += bb;
            *(float4*)&sS[(2 * (o0 + j)) * 144 + n0] = a[j];
        }
    }
    __syncthreads();

    // ---------------- normalize (tid<144) in parallel with WcT load ----------------
    if (tid < 144) {
        float v[32]; float s = 0.f;
        #pragma unroll
        for (int c = 0; c < 32; c++) { float x = sS[(2 * c) * 144 + tid]; v[c] = x; s = fmaf(x, x, s); }
        float nrm = fmaxf(sqrtf(s), 1e-12f);
        float sq = 0.f;
        #pragma unroll
        for (int c = 0; c < 32; c++) { float xn = v[c] / nrm; sXn[tid * 36 + c] = xn; sq = fmaf(xn, xn, sq); }
        sSq[tid] = sq;
    } else {
        // WcT: 64x64 -> [c][64]
        constexpr int NQ = 64 * 64 / 4;
        for (int i = tid - 144; i < NQ; i += TPB - 144) {
            float4 v = ((const float4*)gWc)[i];
            int o = i / 16;
            int c = (i - o * 16) * 4;
            sW[(c + 0) * 64 + o] = v.x;
            sW[(c + 1) * 64 + o] = v.y;
            sW[(c + 2) * 64 + o] = v.z;
            sW[(c + 3) * 64 + o] = v.w;
        }
    }
    __syncthreads();

    // ---------------- pairwise dist + top-9 ----------------
    // part-major: warp processes one m at a time -> xm LDS single-address broadcast,
    // grel coalesced + prefetched. FFMA2 chains reproduce R2's d0..d3 exactly.
    {
        const int row  = (tid < 144) ? tid : tid - 144;
        const int part = (tid < 144) ? 0 : 1;
        ull vv[16];                              // all 32 channels as 16 packed pairs
        {
            const ulonglong2* xr2 = (const ulonglong2*)&sXn[row * 36];
            #pragma unroll
            for (int i = 0; i < 8; i++) { ulonglong2 t = xr2[i]; vv[2*i] = t.x; vv[2*i+1] = t.y; }
        }
        const float sqn = sSq[row];
        float bd[9]; int bi[9];
        #pragma unroll
        for (int k = 0; k < 9; k++) { bd[k] = 3.0e38f; bi[k] = 0; }
        const int m0 = part * 72;
        const float* relp = grel + (size_t)m0 * 144 + row;
        float relv = *relp; relp += 144;
        for (int mm = 0; mm < 72; mm++) {
            const int m = m0 + mm;
            float rel_next = (mm < 71) ? *relp : 0.f; relp += 144;   // prefetch
            const ulonglong2* xm2 = (const ulonglong2*)&sXn[m * 36];
            ulonglong2 t = xm2[0];
            ull d01 = mul2(vv[0], t.x);
            ull d23 = mul2(vv[1], t.y);
            #pragma unroll
            for (int i = 1; i < 8; i++) {
                t = xm2[i];
                d01 = fma2(vv[2*i],   t.x, d01);
                d23 = fma2(vv[2*i+1], t.y, d23);
            }
            float d0, d1, d2, d3;
            unpack2(d01, d0, d1);
            unpack2(d23, d2, d3);
            float dot = (d0 + d1) + (d2 + d3);
            float d = (sqn - 2.0f * dot) + sSq[m] + relv;
            relv = rel_next;
            if (d < bd[8]) {                     // strict-less: ties keep lower index
                bd[8] = d; bi[8] = m;
                #pragma unroll
                for (int j = 8; j > 0; --j) {
                    if (bd[j] < bd[j-1]) {
                        float td = bd[j]; bd[j] = bd[j-1]; bd[j-1] = td;
                        int   ti = bi[j]; bi[j] = bi[j-1]; bi[j-1] = ti;
                    }
                }
            }
        }
        if (part == 1) {                          // stage part-1 lists
            int base = row * 9;
            #pragma unroll
            for (int k = 0; k < 9; k++) { sMrgD[base + k] = bd[k]; sMrgI[base + k] = bi[k]; }
        }
        __syncthreads();
        if (part == 0) {                          // merge (ascending m preserves tie rule)
            int base = row * 9;
            #pragma unroll
            for (int k = 0; k < 9; k++) {
                float d = sMrgD[base + k]; int mi = sMrgI[base + k];
                if (d < bd[8]) {
                    bd[8] = d; bi[8] = mi;
                    #pragma unroll
                    for (int j = 8; j > 0; --j) {
                        if (bd[j] < bd[j-1]) {
                            float td = bd[j]; bd[j] = bd[j-1]; bd[j-1] = td;
                            int   ti = bi[j]; bi[j] = bi[j-1]; bi[j-1] = ti;
                        }
                    }
                }
            }
            #pragma unroll
            for (int k = 0; k < 9; k++) sIdx[row * 9 + k] = bi[k];
        }
    }
    __syncthreads();

    // ---------------- MRConv: max over gathers, then subtract (bit-identical) ----------------
    {
        const int n2 = tid % 144;
        const int g  = tid / 144;          // 0..1 -> channels g*16..g*16+15
        int idx9[9];
        #pragma unroll
        for (int k = 0; k < 9; k++) idx9[k] = sIdx[n2 * 9 + k];
        #pragma unroll
        for (int cc = 0; cc < 16; cc++) {
            int c = g * 16 + cc;
            const float* xrow = &sS[(2 * c) * 144];
            float mx = xrow[idx9[0]];
            #pragma unroll
            for (int k = 1; k < 9; k++) mx = fmaxf(mx, xrow[idx9[k]]);
            sS[(2 * c + 1) * 144 + n2] = mx - xrow[n2];
        }
    }
    __syncthreads();

    // ---------------- hoist W2/F1/F2 LDGs (stores happen after conv barrier) ----------------
    float4 wreg[4];
    {
        #pragma unroll
        for (int k = 0; k < 4; k++) {
            int i = tid + k * TPB;
            if (i < 1024) {
                if (i < 512)      wreg[k] = ((const float4*)gW2)[i];
                else if (i < 768) wreg[k] = ((const float4*)gF1)[i - 512];
                else              wreg[k] = ((const float4*)gF2)[i - 768];
            }
        }
    }

    // ---------------- conv: hc = gelu(WcT @ stacked + bc), 8o x 4n, FFMA2-packed ----------------
    // weight pairs (o,o+1) natural from [c][64] layout; activations duplicated per lane.
    // accumulator lane-lo/hi = adjacent outputs; per-(o,n) chain order identical to scalar.
    {
        const int o0 = q << 3;             // 0..56
        ull A[4][4];                       // [output-pair p][n]
        #pragma unroll
        for (int p = 0; p < 4; p++)
            #pragma unroll
            for (int n = 0; n < 4; n++) A[p][n] = 0ULL;
        #pragma unroll 4
        for (int c = 0; c < 64; c++) {
            ulonglong2 wa = *(const ulonglong2*)&sW[c * 64 + o0];      // pairs (o0,o0+1),(o0+2,o0+3)
            ulonglong2 wb = *(const ulonglong2*)&sW[c * 64 + o0 + 4];  // pairs (o0+4,o0+5),(o0+6,o0+7)
            float4 v = *(const float4*)&sS[c * 144 + n0];
            ull vd0 = pack2(v.x), vd1 = pack2(v.y), vd2 = pack2(v.z), vd3 = pack2(v.w);
            A[0][0] = fma2(wa.x, vd0, A[0][0]); A[0][1] = fma2(wa.x, vd1, A[0][1]);
            A[0][2] = fma2(wa.x, vd2, A[0][2]); A[0][3] = fma2(wa.x, vd3, A[0][3]);
            A[1][0] = fma2(wa.y, vd0, A[1][0]); A[1][1] = fma2(wa.y, vd1, A[1][1]);
            A[1][2] = fma2(wa.y, vd2, A[1][2]); A[1][3] = fma2(wa.y, vd3, A[1][3]);
            A[2][0] = fma2(wb.x, vd0, A[2][0]); A[2][1] = fma2(wb.x, vd1, A[2][1]);
            A[2][2] = fma2(wb.x, vd2, A[2][2]); A[2][3] = fma2(wb.x, vd3, A[2][3]);
            A[3][0] = fma2(wb.y, vd0, A[3][0]); A[3][1] = fma2(wb.y, vd1, A[3][1]);
            A[3][2] = fma2(wb.y, vd2, A[3][2]); A[3][3] = fma2(wb.y, vd3, A[3][3]);
        }
        #pragma unroll
        for (int p = 0; p < 4; p++) {
            float4 lo4, hi4;
            unpack2(A[p][0], lo4.x, hi4.x);
            unpack2(A[p][1], lo4.y, hi4.y);
            unpack2(A[p][2], lo4.z, hi4.z);
            unpack2(A[p][3], lo4.w, hi4.w);
            float be = sB[32 + o0 + 2 * p];
            float bo = sB[32 + o0 + 2 * p + 1];
            lo4.x = gelu_exact(lo4.x + be); lo4.y = gelu_exact(lo4.y + be);
            lo4.z = gelu_exact(lo4.z + be); lo4.w = gelu_exact(lo4.w + be);
            hi4.x = gelu_exact(hi4.x + bo); hi4.y = gelu_exact(hi4.y + bo);
            hi4.z = gelu_exact(hi4.z + bo); hi4.w = gelu_exact(hi4.w + bo);
            *(float4*)&sH[(o0 + 2 * p) * 144 + n0]     = lo4;
            *(float4*)&sH[(o0 + 2 * p + 1) * 144 + n0] = hi4;
        }
    }
    __syncthreads();

    // ---------------- scatter hoisted weights: [W2T | F1T | F2T] ----------------
    {
        #pragma unroll
        for (int k = 0; k < 4; k++) {
            int i = tid + k * TPB;
            if (i < 1024) {
                float4 v = wreg[k];
                if (i < 512) {                    // W2: OUT=32, CIN=64
                    int o = i / 16, c = (i - o * 16) * 4;
                    sW[(c + 0) * 32 + o] = v.x; sW[(c + 1) * 32 + o] = v.y;
                    sW[(c + 2) * 32 + o] = v.z; sW[(c + 3) * 32 + o] = v.w;
                } else if (i < 768) {             // F1: OUT=32, CIN=32
                    int j = i - 512, o = j / 8, c = (j - o * 8) * 4;
                    float* d = sW + 2048;
                    d[(c + 0) * 32 + o] = v.x; d[(c + 1) * 32 + o] = v.y;
                    d[(c + 2) * 32 + o] = v.z; d[(c + 3) * 32 + o] = v.w;
                } else {                          // F2: OUT=32, CIN=32
                    int j = i - 768, o = j / 8, c = (j - o * 8) * 4;
                    float* d = sW + 3072;
                    d[(c + 0) * 32 + o] = v.x; d[(c + 1) * 32 + o] = v.y;
                    d[(c + 2) * 32 + o] = v.z; d[(c + 3) * 32 + o] = v.w;
                }
            }
        }
    }
    __syncthreads();

    // ---------------- fc2 + residual -> sT (in place) ----------------
    {
        int o0 = q << 2;
        float4 a[4];
        gemm4x4T<64, 32>(sW, sH, o0, n0, a);
        #pragma unroll
        for (int j = 0; j < 4; j++) {
            float bb = sB[96 + o0 + j];
            float4 t = *(float4*)&sT[(o0 + j) * 144 + n0];
            a[j].x += bb + t.x; a[j].y += bb + t.y; a[j].z += bb + t.z; a[j].w += bb + t.w;
            *(float4*)&sT[(o0 + j) * 144 + n0] = a[j];
        }
    }
    __syncthreads();

    // ---------------- FFN fc1 -> sS rows 0..31 ----------------
    {
        int o0 = q << 2;
        float4 a[4];
        gemm4x4T<32, 32>(sW + 2048, sT, o0, n0, a);
        #pragma unroll
        for (int j = 0; j < 4; j++) {
            float bb = sB[128 + o0 + j];
            a[j].x = gelu_exact(a[j].x + bb); a[j].y = gelu_exact(a[j].y + bb);
            a[j].z = gelu_exact(a[j].z + bb); a[j].w = gelu_exact(a[j].w + bb);
            *(float4*)&sS[(o0 + j) * 144 + n0] = a[j];
        }
    }
    __syncthreads();

    // ---------------- FFN fc2 + residual -> global ----------------
    {
        int o0 = q << 2;
        float4 a[4];
        gemm4x4T<32, 32>(sW + 3072, sS, o0, n0, a);
        float* go = gout + (size_t)b * 4608;
        #pragma unroll
        for (int j = 0; j < 4; j++) {
            float bb = sB[160 + o0 + j];
            float4 t = *(float4*)&sT[(o0 + j) * 144 + n0];
            a[j].x += bb + t.x; a[j].y += bb + t.y; a[j].z += bb + t.z; a[j].w += bb + t.w;
            *(float4*)&go[(o0 + j) * 144 + n0] = a[j];
        }
    }
}

extern "C" void kernel_launch(void* const* d_in, const int* in_sizes, int n_in,
                              void* d_out, int out_size) {
    (void)n_in; (void)out_size;
    int B = in_sizes[0] / (32 * 144);
    cudaFuncSetAttribute(gcn_kernel, cudaFuncAttributeMaxDynamicSharedMemorySize, SMEM_BYTES);
    gcn_kernel<<<B, TPB, SMEM_BYTES>>>(
        (const float*)d_in[0],  (const float*)d_in[1],  (const float*)d_in[2],
        (const float*)d_in[3],  (const float*)d_in[4],
        (const float*)d_in[5],  (const float*)d_in[6],
        (const float*)d_in[7],  (const float*)d_in[8],
        (const float*)d_in[9],  (const float*)d_in[10],
        (const float*)d_in[11], (const float*)d_in[12],
        (float*)d_out);
}

// round 9
// speedup vs baseline: 1.8201x; 1.0205x over previous
#include <cuda_runtime.h>
#include <math.h>

#define TPB 288
#define SMEM_FLOATS 27328
#define SMEM_BYTES (SMEM_FLOATS * 4)   // 109312 B -> 2 CTAs/SM

typedef unsigned long long ull;

__device__ __forceinline__ float gelu_exact(float x) {
    return 0.5f * x * (1.0f + erff(x * 0.70710678118654752440f));
}

__device__ __forceinline__ ull mul2(ull a, ull b) {
    ull d; asm("mul.rn.f32x2 %0, %1, %2;" : "=l"(d) : "l"(a), "l"(b)); return d;
}
__device__ __forceinline__ ull fma2(ull a, ull b, ull c) {
    ull d; asm("fma.rn.f32x2 %0, %1, %2, %3;" : "=l"(d) : "l"(a), "l"(b), "l"(c)); return d;
}
__device__ __forceinline__ void unpack2(ull v, float& lo, float& hi) {
    unsigned int l, h;
    asm("mov.b64 {%0, %1}, %2;" : "=r"(l), "=r"(h) : "l"(v));
    lo = __uint_as_float(l); hi = __uint_as_float(h);
}
__device__ __forceinline__ ull pack2(float x) {
    ull d; asm("mov.b64 %0, {%1, %1};" : "=l"(d) : "f"(x)); return d;
}

// cooperative transposed weight load: g[o][c] row-major -> s[c][OUT]
template<int OUT, int CIN>
__device__ __forceinline__ void load_wT(const float* __restrict__ g, float* __restrict__ s,
                                        int tid) {
    constexpr int NQ = OUT * CIN / 4;
    for (int i = tid; i < NQ; i += TPB) {
        float4 v = ((const float4*)g)[i];
        int o = i / (CIN / 4);
        int c = (i - o * (CIN / 4)) * 4;
        s[(c + 0) * OUT + o] = v.x;
        s[(c + 1) * OUT + o] = v.y;
        s[(c + 2) * OUT + o] = v.z;
        s[(c + 3) * OUT + o] = v.w;
    }
}

// 4-output x 4-n register tile; weights transposed [c][OUT]; c ascending (R2 numerics)
template<int CIN, int OUT>
__device__ __forceinline__ void gemm4x4T(const float* __restrict__ Wt,
                                         const float* __restrict__ X,
                                         int o0, int n0, float4 a[4]) {
    a[0] = make_float4(0.f, 0.f, 0.f, 0.f);
    a[1] = a[0]; a[2] = a[0]; a[3] = a[0];
    #pragma unroll 8
    for (int c = 0; c < CIN; c++) {
        float4 w = *(const float4*)&Wt[c * OUT + o0];
        float4 v = *(const float4*)&X[c * 144 + n0];
        a[0].x = fmaf(w.x, v.x, a[0].x); a[0].y = fmaf(w.x, v.y, a[0].y);
        a[0].z = fmaf(w.x, v.z, a[0].z); a[0].w = fmaf(w.x, v.w, a[0].w);
        a[1].x = fmaf(w.y, v.x, a[1].x); a[1].y = fmaf(w.y, v.y, a[1].y);
        a[1].z = fmaf(w.y, v.z, a[1].z); a[1].w = fmaf(w.y, v.w, a[1].w);
        a[2].x = fmaf(w.z, v.x, a[2].x); a[2].y = fmaf(w.z, v.y, a[2].y);
        a[2].z = fmaf(w.z, v.z, a[2].z); a[2].w = fmaf(w.z, v.w, a[2].w);
        a[3].x = fmaf(w.w, v.x, a[3].x); a[3].y = fmaf(w.w, v.y, a[3].y);
        a[3].z = fmaf(w.w, v.z, a[3].z); a[3].w = fmaf(w.w, v.w, a[3].w);
    }
}

__global__ void __launch_bounds__(TPB, 2) gcn_kernel(
    const float* __restrict__ gin,  const float* __restrict__ gpos, const float* __restrict__ grel,
    const float* __restrict__ gW1,  const float* __restrict__ gb1,
    const float* __restrict__ gWc,  const float* __restrict__ gbc,
    const float* __restrict__ gW2,  const float* __restrict__ gb2,
    const float* __restrict__ gF1,  const float* __restrict__ gfb1,
    const float* __restrict__ gF2,  const float* __restrict__ gfb2,
    float* __restrict__ gout)
{
    extern __shared__ float sm[];
    float* sW = sm;                   // 4096: W1T -> WcT -> [W2T | F1T | F2T]
    float* sB = sW + 4096;            // 192 biases
    float* sT = sB + 192;             // 4608: tmp = in+pos; later grapher output [c][n]
    float* sS = sT + 4608;            // 9216: stacked [2C][n]; later ffn hidden rows 0..31
    float* sU = sS + 9216;            // 9216: union { sXn/sSq/sIdx/merge | sH conv out }
    float* sXn = sU;                  // [n][c] stride 36
    float* sSq = sU + 5184;           // 144
    int*   sIdx = (int*)(sU + 5376);  // 144*9 ints -> ends at sU+5700
    float* sMrgD = sU + 5704;         // 144*9 floats (part-1 staging)
    int*   sMrgI = (int*)(sU + 7000); // 144*9 ints   -> ends at sU+8296 < 9216
    float* sH = sU;                   // conv output [64][n]

    const int tid = threadIdx.x;
    const int b   = blockIdx.x;
    const int q   = tid / 36;         // 0..7
    const int r   = tid - q * 36;     // 0..35
    const int n0  = r << 2;

    // ---------------- stage 0: W1T + biases + input(+pos) ----------------
    load_wT<32, 32>(gW1, sW, tid);
    if (tid < 32)       sB[tid] = gb1[tid];
    else if (tid < 96)  sB[tid] = gbc[tid - 32];
    else if (tid < 128) sB[tid] = gb2[tid - 96];
    else if (tid < 160) sB[tid] = gfb1[tid - 128];
    else if (tid < 192) sB[tid] = gfb2[tid - 160];
    {
        const float4* gi4 = (const float4*)(gin + (size_t)b * 4608);
        const float4* gp4 = (const float4*)gpos;
        for (int i = tid; i < 1152; i += TPB) {
            float4 a = gi4[i], p = gp4[i];
            a.x += p.x; a.y += p.y; a.z += p.z; a.w += p.w;
            ((float4*)sT)[i] = a;
        }
    }
    __syncthreads();

    // ---------------- fc1: xf = W1 @ tmp + b1 -> sS even rows ----------------
    {
        int o0 = q << 2;
        float4 a[4];
        gemm4x4T<32, 32>(sW, sT, o0, n0, a);
        #pragma unroll
        for (int j = 0; j < 4; j++) {
            float bb = sB[o0 + j];
            a[j].x += bb; a[j].y += bb; a[j].z += bb; a[j].w += bb;
            *(float4*)&sS[(2 * (o0 + j)) * 144 + n0] = a[j];
        }
    }
    __syncthreads();

    // ---------------- normalize (tid<144) in parallel with WcT load ----------------
    if (tid < 144) {
        float v[32]; float s = 0.f;
        #pragma unroll
        for (int c = 0; c < 32; c++) { float x = sS[(2 * c) * 144 + tid]; v[c] = x; s = fmaf(x, x, s); }
        float nrm = fmaxf(sqrtf(s), 1e-12f);
        float sq = 0.f;
        #pragma unroll
        for (int c = 0; c < 32; c++) { float xn = v[c] / nrm; sXn[tid * 36 + c] = xn; sq = fmaf(xn, xn, sq); }
        sSq[tid] = sq;
    } else {
        // WcT: 64x64 -> [c][64]
        constexpr int NQ = 64 * 64 / 4;
        for (int i = tid - 144; i < NQ; i += TPB - 144) {
            float4 v = ((const float4*)gWc)[i];
            int o = i / 16;
            int c = (i - o * 16) * 4;
            sW[(c + 0) * 64 + o] = v.x;
            sW[(c + 1) * 64 + o] = v.y;
            sW[(c + 2) * 64 + o] = v.z;
            sW[(c + 3) * 64 + o] = v.w;
        }
    }
    __syncthreads();

    // ---------------- pairwise dist + top-9 ----------------
    // part-major broadcast layout; m-loop unrolled x2: both dot-products issue before
    // the two (sequential, order-preserving) insert chains -> dots hide sort latency.
    {
        const int row  = (tid < 144) ? tid : tid - 144;
        const int part = (tid < 144) ? 0 : 1;
        ull vv[16];                              // all 32 channels as 16 packed pairs
        {
            const ulonglong2* xr2 = (const ulonglong2*)&sXn[row * 36];
            #pragma unroll
            for (int i = 0; i < 8; i++) { ulonglong2 t = xr2[i]; vv[2*i] = t.x; vv[2*i+1] = t.y; }
        }
        const float sqn = sSq[row];
        float bd[9]; int bi[9];
        #pragma unroll
        for (int k = 0; k < 9; k++) { bd[k] = 3.0e38f; bi[k] = 0; }
        const int m0 = part * 72;
        const float* relp = grel + (size_t)m0 * 144 + row;
        float relv0 = relp[0];
        float relv1 = relp[144];
        relp += 288;
        for (int mm = 0; mm < 72; mm += 2) {
            const int m = m0 + mm;
            float reln0 = 0.f, reln1 = 0.f;
            if (mm < 70) { reln0 = relp[0]; reln1 = relp[144]; }   // prefetch next pair
            relp += 288;
            const ulonglong2* xa2 = (const ulonglong2*)&sXn[m * 36];
            const ulonglong2* xb2 = (const ulonglong2*)&sXn[(m + 1) * 36];
            // dot for m (chains identical to R2's d0..d3)
            ulonglong2 t = xa2[0];
            ull a01 = mul2(vv[0], t.x);
            ull a23 = mul2(vv[1], t.y);
            // dot for m+1
            ulonglong2 u = xb2[0];
            ull b01 = mul2(vv[0], u.x);
            ull b23 = mul2(vv[1], u.y);
            #pragma unroll
            for (int i = 1; i < 8; i++) {
                t = xa2[i];
                a01 = fma2(vv[2*i],   t.x, a01);
                a23 = fma2(vv[2*i+1], t.y, a23);
                u = xb2[i];
                b01 = fma2(vv[2*i],   u.x, b01);
                b23 = fma2(vv[2*i+1], u.y, b23);
            }
            float a0, a1, a2, a3, e0, e1, e2, e3;
            unpack2(a01, a0, a1); unpack2(a23, a2, a3);
            unpack2(b01, e0, e1); unpack2(b23, e2, e3);
            float dota = (a0 + a1) + (a2 + a3);
            float dotb = (e0 + e1) + (e2 + e3);
            float da = (sqn - 2.0f * dota) + sSq[m]     + relv0;
            float db = (sqn - 2.0f * dotb) + sSq[m + 1] + relv1;
            relv0 = reln0; relv1 = reln1;
            // insert m first, then m+1 (ascending order preserves lax.top_k tie rule)
            if (da < bd[8]) {
                bd[8] = da; bi[8] = m;
                #pragma unroll
                for (int j = 8; j > 0; --j) {
                    if (bd[j] < bd[j-1]) {
                        float td = bd[j]; bd[j] = bd[j-1]; bd[j-1] = td;
                        int   ti = bi[j]; bi[j] = bi[j-1]; bi[j-1] = ti;
                    }
                }
            }
            if (db < bd[8]) {
                bd[8] = db; bi[8] = m + 1;
                #pragma unroll
                for (int j = 8; j > 0; --j) {
                    if (bd[j] < bd[j-1]) {
                        float td = bd[j]; bd[j] = bd[j-1]; bd[j-1] = td;
                        int   ti = bi[j]; bi[j] = bi[j-1]; bi[j-1] = ti;
                    }
                }
            }
        }
        if (part == 1) {                          // stage part-1 lists
            int base = row * 9;
            #pragma unroll
            for (int k = 0; k < 9; k++) { sMrgD[base + k] = bd[k]; sMrgI[base + k] = bi[k]; }
        }
        __syncthreads();
        if (part == 0) {                          // merge (ascending m preserves tie rule)
            int base = row * 9;
            #pragma unroll
            for (int k = 0; k < 9; k++) {
                float d = sMrgD[base + k]; int mi = sMrgI[base + k];
                if (d < bd[8]) {
                    bd[8] = d; bi[8] = mi;
                    #pragma unroll
                    for (int j = 8; j > 0; --j) {
                        if (bd[j] < bd[j-1]) {
                            float td = bd[j]; bd[j] = bd[j-1]; bd[j-1] = td;
                            int   ti = bi[j]; bi[j] = bi[j-1]; bi[j-1] = ti;
                        }
                    }
                }
            }
            #pragma unroll
            for (int k = 0; k < 9; k++) sIdx[row * 9 + k] = bi[k];
        }
    }
    __syncthreads();

    // ---------------- MRConv: max over gathers, then subtract (bit-identical) ----------------
    {
        const int n2 = tid % 144;
        const int g  = tid / 144;          // 0..1 -> channels g*16..g*16+15
        int idx9[9];
        #pragma unroll
        for (int k = 0; k < 9; k++) idx9[k] = sIdx[n2 * 9 + k];
        #pragma unroll
        for (int cc = 0; cc < 16; cc++) {
            int c = g * 16 + cc;
            const float* xrow = &sS[(2 * c) * 144];
            float mx = xrow[idx9[0]];
            #pragma unroll
            for (int k = 1; k < 9; k++) mx = fmaxf(mx, xrow[idx9[k]]);
            sS[(2 * c + 1) * 144 + n2] = mx - xrow[n2];
        }
    }
    __syncthreads();

    // ---------------- hoist W2/F1/F2 LDGs (stores happen after conv barrier) ----------------
    float4 wreg[4];
    {
        #pragma unroll
        for (int k = 0; k < 4; k++) {
            int i = tid + k * TPB;
            if (i < 1024) {
                if (i < 512)      wreg[k] = ((const float4*)gW2)[i];
                else if (i < 768) wreg[k] = ((const float4*)gF1)[i - 512];
                else              wreg[k] = ((const float4*)gF2)[i - 768];
            }
        }
    }

    // ---------------- conv: hc = gelu(WcT @ stacked + bc), 8o x 4n, FFMA2-packed ----------------
    {
        const int o0 = q << 3;             // 0..56
        ull A[4][4];                       // [output-pair p][n]
        #pragma unroll
        for (int p = 0; p < 4; p++)
            #pragma unroll
            for (int n = 0; n < 4; n++) A[p][n] = 0ULL;
        #pragma unroll 4
        for (int c = 0; c < 64; c++) {
            ulonglong2 wa = *(const ulonglong2*)&sW[c * 64 + o0];      // pairs (o0,o0+1),(o0+2,o0+3)
            ulonglong2 wb = *(const ulonglong2*)&sW[c * 64 + o0 + 4];  // pairs (o0+4,o0+5),(o0+6,o0+7)
            float4 v = *(const float4*)&sS[c * 144 + n0];
            ull vd0 = pack2(v.x), vd1 = pack2(v.y), vd2 = pack2(v.z), vd3 = pack2(v.w);
            A[0][0] = fma2(wa.x, vd0, A[0][0]); A[0][1] = fma2(wa.x, vd1, A[0][1]);
            A[0][2] = fma2(wa.x, vd2, A[0][2]); A[0][3] = fma2(wa.x, vd3, A[0][3]);
            A[1][0] = fma2(wa.y, vd0, A[1][0]); A[1][1] = fma2(wa.y, vd1, A[1][1]);
            A[1][2] = fma2(wa.y, vd2, A[1][2]); A[1][3] = fma2(wa.y, vd3, A[1][3]);
            A[2][0] = fma2(wb.x, vd0, A[2][0]); A[2][1] = fma2(wb.x, vd1, A[2][1]);
            A[2][2] = fma2(wb.x, vd2, A[2][2]); A[2][3] = fma2(wb.x, vd3, A[2][3]);
            A[3][0] = fma2(wb.y, vd0, A[3][0]); A[3][1] = fma2(wb.y, vd1, A[3][1]);
            A[3][2] = fma2(wb.y, vd2, A[3][2]); A[3][3] = fma2(wb.y, vd3, A[3][3]);
        }
        #pragma unroll
        for (int p = 0; p < 4; p++) {
            float4 lo4, hi4;
            unpack2(A[p][0], lo4.x, hi4.x);
            unpack2(A[p][1], lo4.y, hi4.y);
            unpack2(A[p][2], lo4.z, hi4.z);
            unpack2(A[p][3], lo4.w, hi4.w);
            float be = sB[32 + o0 + 2 * p];
            float bo = sB[32 + o0 + 2 * p + 1];
            lo4.x = gelu_exact(lo4.x + be); lo4.y = gelu_exact(lo4.y + be);
            lo4.z = gelu_exact(lo4.z + be); lo4.w = gelu_exact(lo4.w + be);
            hi4.x = gelu_exact(hi4.x + bo); hi4.y = gelu_exact(hi4.y + bo);
            hi4.z = gelu_exact(hi4.z + bo); hi4.w = gelu_exact(hi4.w + bo);
            *(float4*)&sH[(o0 + 2 * p) * 144 + n0]     = lo4;
            *(float4*)&sH[(o0 + 2 * p + 1) * 144 + n0] = hi4;
        }
    }
    __syncthreads();

    // ---------------- scatter hoisted weights: [W2T | F1T | F2T] ----------------
    {
        #pragma unroll
        for (int k = 0; k < 4; k++) {
            int i = tid + k * TPB;
            if (i < 1024) {
                float4 v = wreg[k];
                if (i < 512) {                    // W2: OUT=32, CIN=64
                    int o = i / 16, c = (i - o * 16) * 4;
                    sW[(c + 0) * 32 + o] = v.x; sW[(c + 1) * 32 + o] = v.y;
                    sW[(c + 2) * 32 + o] = v.z; sW[(c + 3) * 32 + o] = v.w;
                } else if (i < 768) {             // F1: OUT=32, CIN=32
                    int j = i - 512, o = j / 8, c = (j - o * 8) * 4;
                    float* d = sW + 2048;
                    d[(c + 0) * 32 + o] = v.x; d[(c + 1) * 32 + o] = v.y;
                    d[(c + 2) * 32 + o] = v.z; d[(c + 3) * 32 + o] = v.w;
                } else {                          // F2: OUT=32, CIN=32
                    int j = i - 768, o = j / 8, c = (j - o * 8) * 4;
                    float* d = sW + 3072;
                    d[(c + 0) * 32 + o] = v.x; d[(c + 1) * 32 + o] = v.y;
                    d[(c + 2) * 32 + o] = v.z; d[(c + 3) * 32 + o] = v.w;
                }
            }
        }
    }
    __syncthreads();

    // ---------------- fc2 + residual -> sT (in place) ----------------
    {
        int o0 = q << 2;
        float4 a[4];
        gemm4x4T<64, 32>(sW, sH, o0, n0, a);
        #pragma unroll
        for (int j = 0; j < 4; j++) {
            float bb = sB[96 + o0 + j];
            float4 t = *(float4*)&sT[(o0 + j) * 144 + n0];
            a[j].x += bb + t.x; a[j].y += bb + t.y; a[j].z += bb + t.z; a[j].w += bb + t.w;
            *(float4*)&sT[(o0 + j) * 144 + n0] = a[j];
        }
    }
    __syncthreads();

    // ---------------- FFN fc1 -> sS rows 0..31 ----------------
    {
        int o0 = q << 2;
        float4 a[4];
        gemm4x4T<32, 32>(sW + 2048, sT, o0, n0, a);
        #pragma unroll
        for (int j = 0; j < 4; j++) {
            float bb = sB[128 + o0 + j];
            a[j].x = gelu_exact(a[j].x + bb); a[j].y = gelu_exact(a[j].y + bb);
            a[j].z = gelu_exact(a[j].z + bb); a[j].w = gelu_exact(a[j].w + bb);
            *(float4*)&sS[(o0 + j) * 144 + n0] = a[j];
        }
    }
    __syncthreads();

    // ---------------- FFN fc2 + residual -> global ----------------
    {
        int o0 = q << 2;
        float4 a[4];
        gemm4x4T<32, 32>(sW + 3072, sS, o0, n0, a);
        float* go = gout + (size_t)b * 4608;
        #pragma unroll
        for (int j = 0; j < 4; j++) {
            float bb = sB[160 + o0 + j];
            float4 t = *(float4*)&sT[(o0 + j) * 144 + n0];
            a[j].x += bb + t.x; a[j].y += bb + t.y; a[j].z += bb + t.z; a[j].w += bb + t.w;
            *(float4*)&go[(o0 + j) * 144 + n0] = a[j];
        }
    }
}

extern "C" void kernel_launch(void* const* d_in, const int* in_sizes, int n_in,
                              void* d_out, int out_size) {
    (void)n_in; (void)out_size;
    int B = in_sizes[0] / (32 * 144);
    cudaFuncSetAttribute(gcn_kernel, cudaFuncAttributeMaxDynamicSharedMemorySize, SMEM_BYTES);
    gcn_kernel<<<B, TPB, SMEM_BYTES>>>(
        (const float*)d_in[0],  (const float*)d_in[1],  (const float*)d_in[2],
        (const float*)d_in[3],  (const float*)d_in[4],
        (const float*)d_in[5],  (const float*)d_in[6],
        (const float*)d_in[7],  (const float*)d_in[8],
        (const float*)d_in[9],  (const float*)d_in[10],
        (const float*)d_in[11], (const float*)d_in[12],
        (float*)d_out);
}